// round 4
// baseline (speedup 1.0000x reference)
#include <cuda_runtime.h>

// VectorQuantizer: inputs [32, 64, 64, 64] fp32 NCHW (C = D = 64), embedding [512, 64] fp32.
// Replicates the reference's fp32 arithmetic EXACTLY:
//   A   = sum_d fl(x_d * x_d)            (sequential mul-then-add chain, ascending d)
//   e2k = sum_d fl(e_d * e_d)            (sequential mul-then-add chain, ascending d)
//   s_k = FMA-chain_d (x_d * e_dk)       (ascending d, single accumulator == Eigen gebp)
//   dist_k = fl( fl(A + e2k) - fl(2*s_k) )
// argmin with strict < ascending k == jnp.argmin first-occurrence tie-break.

#define NUM_CODES 512
#define DIMS      64
#define TPB       512
#define NPIX      (32 * 64 * 64)          // 131072 pixels
#define IMG_STRIDE (64 * 4096)            // floats per image (C*H*W)
#define SMEM_FLOATS (DIMS * NUM_CODES + NUM_CODES)
#define SMEM_BYTES  (SMEM_FLOATS * 4)     // 133120 bytes

__device__ __forceinline__ unsigned long long ffma2(unsigned long long a,
                                                    unsigned long long b,
                                                    unsigned long long c) {
    unsigned long long d;
    asm("fma.rn.f32x2 %0, %1, %2, %3;" : "=l"(d) : "l"(a), "l"(b), "l"(c));
    return d;
}

__device__ __forceinline__ unsigned long long pack2(float x) {
    unsigned long long r;
    asm("mov.b64 %0, {%1, %1};" : "=l"(r) : "f"(x));
    return r;
}

__device__ __forceinline__ void unpack2(unsigned long long v, float& lo, float& hi) {
    asm("mov.b64 {%0, %1}, %2;" : "=f"(lo), "=f"(hi) : "l"(v));
}

__global__ __launch_bounds__(TPB, 1)
void vq_kernel(const float* __restrict__ in,
               const float* __restrict__ emb,
               float* __restrict__ out) {
    extern __shared__ float smem[];
    float* Es  = smem;                      // transposed codebook [DIMS][NUM_CODES]
    float* e2s = smem + DIMS * NUM_CODES;   // ||e_k||^2, [NUM_CODES]

    const int tid = threadIdx.x;

    // ---- Stage codebook into shared memory, transposed, + per-code squared norm ----
    // thread t owns code k = t (TPB == NUM_CODES).
    // e2 = sequential mul-then-add chain ascending d (matches XLA reduce emitter: no FMA,
    // no reassociation).
    {
        const float4* row = reinterpret_cast<const float4*>(emb + tid * DIMS);
        float s = 0.0f;
        #pragma unroll
        for (int j = 0; j < DIMS / 4; ++j) {
            float4 v = row[j];
            Es[(4 * j + 0) * NUM_CODES + tid] = v.x;
            Es[(4 * j + 1) * NUM_CODES + tid] = v.y;
            Es[(4 * j + 2) * NUM_CODES + tid] = v.z;
            Es[(4 * j + 3) * NUM_CODES + tid] = v.w;
            s = __fadd_rn(s, __fmul_rn(v.x, v.x));
            s = __fadd_rn(s, __fmul_rn(v.y, v.y));
            s = __fadd_rn(s, __fmul_rn(v.z, v.z));
            s = __fadd_rn(s, __fmul_rn(v.w, v.w));
        }
        e2s[tid] = s;
    }
    __syncthreads();

    const int totalThreads = gridDim.x * TPB;

    for (int n = blockIdx.x * TPB + tid; n < NPIX; n += totalThreads) {
        // pixel n = b*4096 + h*64 + w ; element (n, d) lives at b*IMG_STRIDE + d*CH_STRIDE + (h*64+w)
        const int base = ((n >> 12) * IMG_STRIDE) + (n & 4095);
        const float* px = in + base;

        float x[DIMS];
        #pragma unroll
        for (int d = 0; d < DIMS; ++d) x[d] = px[d << 12];

        // A = ||x||^2 : strict sequential mul-then-add chain, ascending d.
        float A = 0.0f;
        #pragma unroll
        for (int d = 0; d < DIMS; ++d) A = __fadd_rn(A, __fmul_rn(x[d], x[d]));

        float best  = 3.402823466e+38f;
        int   bestk = 0;

        #pragma unroll 1
        for (int k0 = 0; k0 < NUM_CODES; k0 += 16) {
            unsigned long long acc[8];
            #pragma unroll
            for (int j = 0; j < 8; ++j) acc[j] = 0ull;

            // s_k: single-accumulator FMA chain over d ascending (per f32x2 lane, IEEE fp32
            // fma.rn each step) — bitwise identical to Eigen's sequential-k gebp accumulation.
            #pragma unroll
            for (int d = 0; d < DIMS; ++d) {
                const unsigned long long xp = pack2(x[d]);
                const ulonglong2* p =
                    reinterpret_cast<const ulonglong2*>(Es + d * NUM_CODES + k0);
                ulonglong2 q0 = p[0];
                ulonglong2 q1 = p[1];
                ulonglong2 q2 = p[2];
                ulonglong2 q3 = p[3];
                acc[0] = ffma2(xp, q0.x, acc[0]);
                acc[1] = ffma2(xp, q0.y, acc[1]);
                acc[2] = ffma2(xp, q1.x, acc[2]);
                acc[3] = ffma2(xp, q1.y, acc[3]);
                acc[4] = ffma2(xp, q2.x, acc[4]);
                acc[5] = ffma2(xp, q2.y, acc[5]);
                acc[6] = ffma2(xp, q3.x, acc[6]);
                acc[7] = ffma2(xp, q3.y, acc[7]);
            }

            // finalize 16 codes in ascending k (strict < == first-occurrence argmin).
            // dist = fl( fl(A + e2k) - fl(2*s) )  -- exact reference rounding sequence.
            #pragma unroll
            for (int j = 0; j < 8; ++j) {
                float sl, sh;
                unpack2(acc[j], sl, sh);
                const int kl = k0 + 2 * j;
                const float Tl = __fadd_rn(A, e2s[kl]);
                const float Th = __fadd_rn(A, e2s[kl + 1]);
                const float distl = __fsub_rn(Tl, __fmul_rn(2.0f, sl));
                const float disth = __fsub_rn(Th, __fmul_rn(2.0f, sh));
                if (distl < best) { best = distl; bestk = kl; }
                if (disth < best) { best = disth; bestk = kl + 1; }
            }
        }

        // ---- Write the winning code vector back, NCHW-strided ----
        float* po = out + base;
        #pragma unroll
        for (int d = 0; d < DIMS; ++d) po[d << 12] = Es[d * NUM_CODES + bestk];
    }
}

extern "C" void kernel_launch(void* const* d_in, const int* in_sizes, int n_in,
                              void* d_out, int out_size) {
    const float* in  = (const float*)d_in[0];   // inputs  [32,64,64,64] fp32
    const float* emb = (const float*)d_in[1];   // embedding [512,64] fp32
    float* out = (float*)d_out;

    cudaFuncSetAttribute(vq_kernel, cudaFuncAttributeMaxDynamicSharedMemorySize, SMEM_BYTES);
    vq_kernel<<<152, TPB, SMEM_BYTES>>>(in, emb, out);
}

// round 5
// speedup vs baseline: 1.4497x; 1.4497x over previous
#include <cuda_runtime.h>

// VectorQuantizer: inputs [32, 64, 64, 64] fp32 NCHW (C = D = 64), embedding [512, 64] fp32.
// Bit-exact replication of the reference fp32 arithmetic:
//   A   = sum_d fl(x_d * x_d)            (sequential mul-then-add chain, ascending d)
//   e2k = sum_d fl(e_d * e_d)            (sequential mul-then-add chain, ascending d)
//   s_k = FMA-chain_d (x_d * e_dk)       (ascending d, single accumulator)
//   dist_k = fl( fl(A + e2k) + fl(-2*s_k) )   (== fl(fl(A+e2k) - fl(2*s_k)) bitwise)
//   argmin: first-occurrence (u64 key = fp32_bits(dist)<<32 | k, min-reduce; dist > 0)
//   out = fl(x + fl(q - x))              (exact straight-through-estimator rounding)
//
// Perf: 2 pixels per thread share every codebook LDS.128 -> smem-port demand halves
// (was the binding pipe at 2x FMA demand). TPB=256, persistent grid.

#define NUM_CODES 512
#define DIMS      64
#define TPB       256
#define NPIX      (32 * 64 * 64)          // 131072 pixels
#define NPAIRS    (NPIX / 2)              // 65536: pair (n, n+NPAIRS)
#define IMG_STRIDE (64 * 4096)            // floats per image (C*H*W)
#define PAIR_OFF  (16 * IMG_STRIDE)       // pixel n+65536 is image b+16, same (h,w)
#define SMEM_FLOATS (DIMS * NUM_CODES + NUM_CODES)
#define SMEM_BYTES  (SMEM_FLOATS * 4)     // 133120 bytes
#define GRID 152

typedef unsigned long long ull;

__device__ __forceinline__ ull ffma2(ull a, ull b, ull c) {
    ull d;
    asm("fma.rn.f32x2 %0, %1, %2, %3;" : "=l"(d) : "l"(a), "l"(b), "l"(c));
    return d;
}
__device__ __forceinline__ ull fadd2(ull a, ull b) {
    ull d;
    asm("add.rn.f32x2 %0, %1, %2;" : "=l"(d) : "l"(a), "l"(b));
    return d;
}
__device__ __forceinline__ ull fmul2(ull a, ull b) {
    ull d;
    asm("mul.rn.f32x2 %0, %1, %2;" : "=l"(d) : "l"(a), "l"(b));
    return d;
}
__device__ __forceinline__ ull pack2(float x) {
    ull r;
    asm("mov.b64 %0, {%1, %1};" : "=l"(r) : "f"(x));
    return r;
}
__device__ __forceinline__ void unpack2(ull v, float& lo, float& hi) {
    asm("mov.b64 {%0, %1}, %2;" : "=f"(lo), "=f"(hi) : "l"(v));
}
__device__ __forceinline__ ull umin64(ull a, ull b) { return a < b ? a : b; }

__global__ __launch_bounds__(TPB, 1)
void vq_kernel(const float* __restrict__ in,
               const float* __restrict__ emb,
               float* __restrict__ out) {
    extern __shared__ float smem[];
    float* Es  = smem;                      // transposed codebook [DIMS][NUM_CODES]
    float* e2s = smem + DIMS * NUM_CODES;   // ||e_k||^2, [NUM_CODES]

    const int tid = threadIdx.x;

    // ---- Stage codebook into smem, transposed, + sequential-chain squared norms ----
    // thread t owns codes t and t+256.
    #pragma unroll
    for (int kk = 0; kk < 2; ++kk) {
        const int k = tid + kk * TPB;
        const float4* row = reinterpret_cast<const float4*>(emb + k * DIMS);
        float s = 0.0f;
        #pragma unroll
        for (int j = 0; j < DIMS / 4; ++j) {
            float4 v = row[j];
            Es[(4 * j + 0) * NUM_CODES + k] = v.x;
            Es[(4 * j + 1) * NUM_CODES + k] = v.y;
            Es[(4 * j + 2) * NUM_CODES + k] = v.z;
            Es[(4 * j + 3) * NUM_CODES + k] = v.w;
            s = __fadd_rn(s, __fmul_rn(v.x, v.x));
            s = __fadd_rn(s, __fmul_rn(v.y, v.y));
            s = __fadd_rn(s, __fmul_rn(v.z, v.z));
            s = __fadd_rn(s, __fmul_rn(v.w, v.w));
        }
        e2s[k] = s;
    }
    __syncthreads();

    const ull neg2 = pack2(-2.0f);
    const int totalThreads = GRID * TPB;

    for (int p = blockIdx.x * TPB + tid; p < NPAIRS; p += totalThreads) {
        // pixel n : element (n, d) at (n>>12)*IMG_STRIDE + d*4096 + (n&4095)
        const int base0 = ((p >> 12) * IMG_STRIDE) + (p & 4095);
        const float* px0 = in + base0;
        const float* px1 = in + base0 + PAIR_OFF;

        float x0[DIMS], x1[DIMS];
        #pragma unroll
        for (int d = 0; d < DIMS; ++d) x0[d] = px0[d << 12];
        #pragma unroll
        for (int d = 0; d < DIMS; ++d) x1[d] = px1[d << 12];

        // A = ||x||^2 : strict sequential mul-then-add chain, ascending d.
        float A0 = 0.0f, A1 = 0.0f;
        #pragma unroll
        for (int d = 0; d < DIMS; ++d) A0 = __fadd_rn(A0, __fmul_rn(x0[d], x0[d]));
        #pragma unroll
        for (int d = 0; d < DIMS; ++d) A1 = __fadd_rn(A1, __fmul_rn(x1[d], x1[d]));
        const ull A0p = pack2(A0);
        const ull A1p = pack2(A1);

        ull best0 = 0xFFFFFFFFFFFFFFFFull;
        ull best1 = 0xFFFFFFFFFFFFFFFFull;

        #pragma unroll 1
        for (int k0 = 0; k0 < NUM_CODES; k0 += 16) {
            ull acc0[8], acc1[8];
            #pragma unroll
            for (int j = 0; j < 8; ++j) { acc0[j] = 0ull; acc1[j] = 0ull; }

            // s_k: single-accumulator FMA chain over d ascending (per f32x2 lane).
            // One set of codebook loads feeds BOTH pixels.
            #pragma unroll
            for (int d = 0; d < DIMS; ++d) {
                const ull xp0 = pack2(x0[d]);
                const ull xp1 = pack2(x1[d]);
                const ulonglong2* ptr =
                    reinterpret_cast<const ulonglong2*>(Es + d * NUM_CODES + k0);
                ulonglong2 q0 = ptr[0];
                ulonglong2 q1 = ptr[1];
                ulonglong2 q2 = ptr[2];
                ulonglong2 q3 = ptr[3];
                acc0[0] = ffma2(xp0, q0.x, acc0[0]);  acc1[0] = ffma2(xp1, q0.x, acc1[0]);
                acc0[1] = ffma2(xp0, q0.y, acc0[1]);  acc1[1] = ffma2(xp1, q0.y, acc1[1]);
                acc0[2] = ffma2(xp0, q1.x, acc0[2]);  acc1[2] = ffma2(xp1, q1.x, acc1[2]);
                acc0[3] = ffma2(xp0, q1.y, acc0[3]);  acc1[3] = ffma2(xp1, q1.y, acc1[3]);
                acc0[4] = ffma2(xp0, q2.x, acc0[4]);  acc1[4] = ffma2(xp1, q2.x, acc1[4]);
                acc0[5] = ffma2(xp0, q2.y, acc0[5]);  acc1[5] = ffma2(xp1, q2.y, acc1[5]);
                acc0[6] = ffma2(xp0, q3.x, acc0[6]);  acc1[6] = ffma2(xp1, q3.x, acc1[6]);
                acc0[7] = ffma2(xp0, q3.y, acc0[7]);  acc1[7] = ffma2(xp1, q3.y, acc1[7]);
            }

            // Finalize 16 codes: dist = fl( fl(A + e2k) + fl(-2*s) )   (packed, per-lane IEEE)
            // Key = fp32bits(dist)<<32 | k  (dist ~ 64 > 0 -> bits monotone);
            // min over keys == first-occurrence argmin.
            const ull* e2q = reinterpret_cast<const ull*>(e2s + k0);   // 8x u64 (2 e2 each)
            ull keys0[16], keys1[16];
            #pragma unroll
            for (int j = 0; j < 8; ++j) {
                const ull e2j = e2q[j];
                const ull d0 = fadd2(fadd2(A0p, e2j), fmul2(neg2, acc0[j]));
                const ull d1 = fadd2(fadd2(A1p, e2j), fmul2(neg2, acc1[j]));
                float l0, h0, l1, h1;
                unpack2(d0, l0, h0);
                unpack2(d1, l1, h1);
                const ull kl = (ull)(unsigned)(k0 + 2 * j);
                keys0[2 * j]     = ((ull)__float_as_uint(l0) << 32) | kl;
                keys0[2 * j + 1] = ((ull)__float_as_uint(h0) << 32) | (kl + 1);
                keys1[2 * j]     = ((ull)__float_as_uint(l1) << 32) | kl;
                keys1[2 * j + 1] = ((ull)__float_as_uint(h1) << 32) | (kl + 1);
            }
            #pragma unroll
            for (int stride = 8; stride >= 1; stride >>= 1) {
                #pragma unroll
                for (int j = 0; j < stride; ++j) {
                    keys0[j] = umin64(keys0[j], keys0[j + stride]);
                    keys1[j] = umin64(keys1[j], keys1[j + stride]);
                }
            }
            best0 = umin64(best0, keys0[0]);
            best1 = umin64(best1, keys1[0]);
        }

        const int bk0 = (int)(unsigned)best0;
        const int bk1 = (int)(unsigned)best1;

        // ---- Write back with exact STE rounding: out = fl(x + fl(q - x)) ----
        float* po0 = out + base0;
        float* po1 = out + base0 + PAIR_OFF;
        #pragma unroll
        for (int d = 0; d < DIMS; ++d) {
            const float q0v = Es[d * NUM_CODES + bk0];
            const float q1v = Es[d * NUM_CODES + bk1];
            po0[d << 12] = __fadd_rn(x0[d], __fsub_rn(q0v, x0[d]));
            po1[d << 12] = __fadd_rn(x1[d], __fsub_rn(q1v, x1[d]));
        }
    }
}

extern "C" void kernel_launch(void* const* d_in, const int* in_sizes, int n_in,
                              void* d_out, int out_size) {
    const float* in  = (const float*)d_in[0];   // inputs  [32,64,64,64] fp32
    const float* emb = (const float*)d_in[1];   // embedding [512,64] fp32
    float* out = (float*)d_out;

    cudaFuncSetAttribute(vq_kernel, cudaFuncAttributeMaxDynamicSharedMemorySize, SMEM_BYTES);
    vq_kernel<<<GRID, TPB, SMEM_BYTES>>>(in, emb, out);
}